// round 15
// baseline (speedup 1.0000x reference)
#include <cuda_runtime.h>
#include <cuda_bf16.h>
#include <stdint.h>
#include <math.h>

#define CBN 6
#define CSZ 1024
#define TPB 256
#define RPC 128          // rows per CTA (16 per warp)  — proven R12 shape
#define EPS 0.25f        // rescue window: required ~0.11, 2.3x margin (proven R12)
#define QMAX 320         // per-warp queue entries; flush keeps 256 headroom

// per-lane-region b-frag layout: region (0..31) = g*4+t, stride 130 uint2
// (=1040B, odd 16B multiple -> conflict-free LDS.128), element nt at +nt.
__device__ __align__(16) uint2 g_bfrag[CBN * 32 * 130];
__device__ float  g_c2[CBN * CSZ];
__device__ float  g_L[CBN * CSZ];
__device__ float  g_p2[CBN * CSZ];
__device__ int    g_lc[CBN];
__device__ double g_part[CBN * 256];
__device__ unsigned int g_ctr = 0;

struct __align__(16) Smem {
    uint4  bfrag[32 * 65];            // 33280B
    float4 xfp[2 * RPC];              //  4096B exact fp32 x (rescue)
    unsigned short xaf[RPC * 8];      //  2048B bf16(-2x) a-frags
    float  x2sh[RPC];                 //   512B
    float  bitsv[RPC];                //   512B
    unsigned int qdat[8 * QMAX];      // 10240B per-warp rescue queues
    unsigned long long rbest[RPC];    //  1024B packed (val_bits<<32)|s per row
    double dscr[TPB];                 //  2048B
    int    flag;
};

__device__ __forceinline__ float sqrt_approx(float v) {
    float r; asm("sqrt.approx.f32 %0, %1;" : "=f"(r) : "f"(v)); return r;
}

__device__ __forceinline__ void hmma16816(float& d0, float& d1, float& d2, float& d3,
                                          uint32_t a0, uint32_t a1, uint32_t a2, uint32_t a3,
                                          uint32_t b0, uint32_t b1) {
    asm volatile(
        "mma.sync.aligned.m16n8k16.row.col.f32.bf16.bf16.f32 "
        "{%0,%1,%2,%3}, {%4,%5,%6,%7}, {%8,%9}, {%10,%11,%12,%13};"
        : "=f"(d0), "=f"(d1), "=f"(d2), "=f"(d3)
        : "r"(a0), "r"(a1), "r"(a2), "r"(a3), "r"(b0), "r"(b1),
          "f"(0.0f), "f"(0.0f), "f"(0.0f), "f"(0.0f));
}

// ---------------- prep: per-cb tables (proven numerics chain) ----------------
__global__ void __launch_bounds__(TPB) prep_kernel(
    const float* __restrict__ codebook,
    const float* __restrict__ logits)
{
    __shared__ float scr[TPB];
    const int tid = threadIdx.x;
    const int cb  = blockIdx.x;

    float4 lv = *reinterpret_cast<const float4*>(logits + (size_t)cb * CSZ + tid * 4);
    float lm = fmaxf(fmaxf(lv.x, lv.y), fmaxf(lv.z, lv.w));
    scr[tid] = lm; __syncthreads();
    #pragma unroll
    for (int off = 128; off > 0; off >>= 1) {
        if (tid < off) scr[tid] = fmaxf(scr[tid], scr[tid + off]);
        __syncthreads();
    }
    const float mx = scr[0]; __syncthreads();
    float lmn = fminf(fminf(lv.x, lv.y), fminf(lv.z, lv.w));
    scr[tid] = lmn; __syncthreads();
    #pragma unroll
    for (int off = 128; off > 0; off >>= 1) {
        if (tid < off) scr[tid] = fminf(scr[tid], scr[tid + off]);
        __syncthreads();
    }
    const bool lc = (scr[0] == mx);
    __syncthreads();
    float es = expf(lv.x - mx) + expf(lv.y - mx) + expf(lv.z - mx) + expf(lv.w - mx);
    scr[tid] = es; __syncthreads();
    #pragma unroll
    for (int off = 128; off > 0; off >>= 1) {
        if (tid < off) scr[tid] += scr[tid + off];
        __syncthreads();
    }
    const float lnS = logf(scr[0]);

    const float INV_LOG2 = 1.4426950408889634f;
    #pragma unroll
    for (int j = 0; j < 4; j++) {
        int s = tid * 4 + j;
        const float4* cp = reinterpret_cast<const float4*>(codebook + ((size_t)cb * CSZ + s) * 8);
        float4 c0 = cp[0], c1 = cp[1];
        float q0=c0.x*c0.x,q1=c0.y*c0.y,q2=c0.z*c0.z,q3=c0.w*c0.w;
        float q4=c1.x*c1.x,q5=c1.y*c1.y,q6=c1.z*c1.z,q7=c1.w*c1.w;
        float c2 = ((((((q0+q1)+q2)+q3)+q4)+q5)+q6)+q7;
        float v  = (j==0)?lv.x:(j==1)?lv.y:(j==2)?lv.z:lv.w;
        float p2 = ((v - mx) - lnS) * (-INV_LOG2);
        size_t gi = (size_t)cb * CSZ + s;
        g_c2[gi] = c2;
        g_L[gi]  = p2 / 0.005f;
        g_p2[gi] = p2;
        unsigned short e[8];
        e[0]=__bfloat16_as_ushort(__float2bfloat16_rn(c0.x));
        e[1]=__bfloat16_as_ushort(__float2bfloat16_rn(c0.y));
        e[2]=__bfloat16_as_ushort(__float2bfloat16_rn(c0.z));
        e[3]=__bfloat16_as_ushort(__float2bfloat16_rn(c0.w));
        e[4]=__bfloat16_as_ushort(__float2bfloat16_rn(c1.x));
        e[5]=__bfloat16_as_ushort(__float2bfloat16_rn(c1.y));
        e[6]=__bfloat16_as_ushort(__float2bfloat16_rn(c1.z));
        e[7]=__bfloat16_as_ushort(__float2bfloat16_rn(c1.w));
        unsigned short c2b = __bfloat16_as_ushort(__float2bfloat16_rn(c2));
        int nt = s >> 3, g = s & 7;
        uint2* base = &g_bfrag[(size_t)cb * 4160];
        #pragma unroll
        for (int t = 0; t < 4; t++) {
            uint32_t lo = (uint32_t)e[2*t] | ((uint32_t)e[2*t+1] << 16);
            uint32_t hi = (t == 0) ? (uint32_t)c2b : 0u;   // k8 = c2 (pairs a-frag 1.0)
            base[(g * 4 + t) * 130 + nt] = make_uint2(lo, hi);
        }
    }
    if (tid == 0) g_lc[cb] = lc ? 1 : 0;
}

// ---------------- main ----------------
__global__ void __launch_bounds__(TPB, 4)
ecvq_kernel(const float* __restrict__ x,
            const float* __restrict__ codebook,
            float* __restrict__ out, int B)
{
    extern __shared__ unsigned char smem_raw[];
    Smem* sm = reinterpret_cast<Smem*>(smem_raw);

    const int tid = threadIdx.x;
    const int cb  = blockIdx.x;
    const int rowBase = blockIdx.y * RPC;
    const float FINF = __int_as_float(0x7f800000);
    const size_t gb = (size_t)cb * CSZ;

    // ---- copy b-frag table from gmem (2080 uint4) ----
    {
        const uint4* src = reinterpret_cast<const uint4*>(&g_bfrag[(size_t)cb * 4160]);
        uint4* dst = sm->bfrag;
        #pragma unroll
        for (int i = 0; i < 8; i++) dst[tid + i * TPB] = src[tid + i * TPB];
        if (tid < 2080 - 8 * TPB) dst[tid + 8 * TPB] = src[tid + 8 * TPB];
    }
    const bool lc = (g_lc[cb] != 0);
    const float Lc = __ldg(&g_L[gb]);   // constant L when lc

    // ---- stage x (all 256 threads: half a row each) + init rbest ----
    {
        int r = tid >> 1;               // row 0..127
        int h = tid & 1;                // half
        int grow = rowBase + r;
        const float4* xpp = reinterpret_cast<const float4*>(
            x + (size_t)grow * (CBN * 8) + cb * 8) + h;
        float4 p = *xpp;
        sm->xfp[2 * r + h] = p;
        unsigned short* xa = &sm->xaf[r * 8 + h * 4];
        xa[0] = __bfloat16_as_ushort(__float2bfloat16_rn(-2.0f * p.x));
        xa[1] = __bfloat16_as_ushort(__float2bfloat16_rn(-2.0f * p.y));
        xa[2] = __bfloat16_as_ushort(__float2bfloat16_rn(-2.0f * p.z));
        xa[3] = __bfloat16_as_ushort(__float2bfloat16_rn(-2.0f * p.w));
        if (h == 0) sm->rbest[r] = ((unsigned long long)0x7f800000u << 32) | 0xFFFFFFFFull;
    }
    __syncthreads();
    // exact x2 (one thread per row, same fp32 chain as proven)
    if (tid < RPC) {
        float4 p0 = sm->xfp[2 * tid], p1 = sm->xfp[2 * tid + 1];
        float q0=p0.x*p0.x,q1=p0.y*p0.y,q2=p0.z*p0.z,q3=p0.w*p0.w;
        float q4=p1.x*p1.x,q5=p1.y*p1.y,q6=p1.z*p1.z,q7=p1.w*p1.w;
        sm->x2sh[tid] = ((((((q0+q1)+q2)+q3)+q4)+q5)+q6)+q7;
    }
    __syncthreads();

    // ---- warp tiling: each warp owns 16 rows ----
    const int warp = tid >> 5, lane = tid & 31;
    const int g = lane >> 2, t = lane & 3;
    const int r0 = warp * 16 + g, r1 = r0 + 8;

    const uint32_t a0 = *reinterpret_cast<const uint32_t*>(&sm->xaf[r0 * 8 + t * 2]);
    const uint32_t a1 = *reinterpret_cast<const uint32_t*>(&sm->xaf[r1 * 8 + t * 2]);
    const uint32_t ac = (t == 0) ? 0x00003F80u : 0u;   // bf16(1.0) at k8
    const unsigned lt = (1u << lane) - 1u;

    const char* bp = reinterpret_cast<const char*>(sm->bfrag) + lane * 1040;

    // exact rescore + publish (bit-exact proven chain; batched, warp-cooperative)
    auto flushq = [&](int n) {
        for (int b = 0; b < n; b += 32) {
            int i = b + lane;
            if (i < n) {
                unsigned e = sm->qdat[warp * QMAX + i];
                int s = (int)(e & 1023u), rl = (int)(e >> 10);
                int r = warp * 16 + rl;
                const float4* cp = reinterpret_cast<const float4*>(codebook + (gb + s) * 8);
                float4 ca = __ldg(cp), cv = __ldg(cp + 1);
                float4 pa = sm->xfp[2 * r], pb = sm->xfp[2 * r + 1];
                float xc = pa.x * ca.x;
                xc = fmaf(pa.y, ca.y, xc); xc = fmaf(pa.z, ca.z, xc); xc = fmaf(pa.w, ca.w, xc);
                xc = fmaf(pb.x, cv.x, xc); xc = fmaf(pb.y, cv.y, xc);
                xc = fmaf(pb.z, cv.z, xc); xc = fmaf(pb.w, cv.w, xc);
                float d2 = fmaf(-2.0f, xc, sm->x2sh[r]) + __ldg(&g_c2[gb + s]);
                float L  = lc ? Lc : __ldg(&g_L[gb + s]);
                float val = sqrt_approx(fmaxf(d2, 0.0f)) + L;
                unsigned long long pk =
                    ((unsigned long long)__float_as_uint(val) << 32) | (unsigned long long)(unsigned)s;
                atomicMin(&sm->rbest[r], pk);
            }
        }
    };

    int qn = 0;   // warp-uniform queue count (ballot/popc maintained)

    #define PUSHQ(pred, sval, rlocal) do { \
        unsigned mk = __ballot_sync(0xffffffffu, (pred)); \
        if (pred) sm->qdat[warp * QMAX + qn + __popc(mk & lt)] = \
            (unsigned)((sval) | ((rlocal) << 10)); \
        qn += __popc(mk); \
    } while (0)

    // push body shared by phases B and C (candidate ids derived from it)
    #define SCAN_PUSH(itv, th0, th1) do { \
        uint4 q = *reinterpret_cast<const uint4*>(bp + (itv) * 16); \
        float d0, d1, d2, d3, e0, e1, e2, e3; \
        hmma16816(d0, d1, d2, d3, a0, a1, ac, ac, q.x, q.y); \
        hmma16816(e0, e1, e2, e3, a0, a1, ac, ac, q.z, q.w); \
        float n0 = fminf(fminf(d0, d1), fminf(e0, e1)); \
        float n1 = fminf(fminf(d2, d3), fminf(e2, e3)); \
        m0 = fminf(m0, n0); m1 = fminf(m1, n1); \
        bool anyT = (n0 < (th0)) | (n1 < (th1)); \
        if (__ballot_sync(0xffffffffu, anyT)) { \
            if (qn >= QMAX - 256) { __syncwarp(); flushq(qn); __syncwarp(); qn = 0; } \
            int sA = (2 * (itv)) * 8 + 2 * t; \
            int sB = sA + 8; \
            PUSHQ(d0 < (th0), sA,     g); \
            PUSHQ(d1 < (th0), sA + 1, g); \
            PUSHQ(d2 < (th1), sA,     g + 8); \
            PUSHQ(d3 < (th1), sA + 1, g + 8); \
            PUSHQ(e0 < (th0), sB,     g); \
            PUSHQ(e1 < (th0), sB + 1, g); \
            PUSHQ(e2 < (th1), sB,     g + 8); \
            PUSHQ(e3 < (th1), sB + 1, g + 8); \
        } \
    } while (0)

    // ===== Phase A: branchless min-scan of H1 (it 0..31) =====
    float m0 = FINF, m1 = FINF;
    #pragma unroll 8
    for (int it = 0; it < 32; it++) {
        uint4 q = *reinterpret_cast<const uint4*>(bp + it * 16);
        float d0, d1, d2, d3, e0, e1, e2, e3;
        hmma16816(d0, d1, d2, d3, a0, a1, ac, ac, q.x, q.y);
        hmma16816(e0, e1, e2, e3, a0, a1, ac, ac, q.z, q.w);
        m0 = fminf(m0, fminf(fminf(d0, d1), fminf(e0, e1)));
        m1 = fminf(m1, fminf(fminf(d2, d3), fminf(e2, e3)));
    }
    m0 = fminf(m0, __shfl_xor_sync(0xffffffffu, m0, 1));
    m0 = fminf(m0, __shfl_xor_sync(0xffffffffu, m0, 2));
    m1 = fminf(m1, __shfl_xor_sync(0xffffffffu, m1, 1));
    m1 = fminf(m1, __shfl_xor_sync(0xffffffffu, m1, 2));

    const float thrA0 = lc ? m0 + EPS : FINF;   // superset window: m(H1) >= m(all)
    const float thrA1 = lc ? m1 + EPS : FINF;

    // ===== Phase B: scan H2 (it 32..63), push vs fixed thrA, accumulate min =====
    #pragma unroll 8
    for (int it = 32; it < 64; it++) {
        SCAN_PUSH(it, thrA0, thrA1);
    }
    m0 = fminf(m0, __shfl_xor_sync(0xffffffffu, m0, 1));
    m0 = fminf(m0, __shfl_xor_sync(0xffffffffu, m0, 2));
    m1 = fminf(m1, __shfl_xor_sync(0xffffffffu, m1, 1));
    m1 = fminf(m1, __shfl_xor_sync(0xffffffffu, m1, 2));

    const float thr0 = lc ? m0 + EPS : FINF;    // final window (global min)
    const float thr1 = lc ? m1 + EPS : FINF;

    // ===== Phase C: rescan H1 (it 0..31) with final threshold =====
    #pragma unroll 8
    for (int it = 0; it < 32; it++) {
        SCAN_PUSH(it, thr0, thr1);
    }
    __syncwarp();
    flushq(qn);
    __syncwarp();

    // ---- epilogue: lanes 0..15 write their row's winner ----
    if (lane < 16) {
        int r = warp * 16 + lane;
        unsigned long long w = sm->rbest[r];
        int bi = (int)(unsigned)(w & 0xFFFFFFFFull);
        int grow = rowBase + r;
        const float4* cp = reinterpret_cast<const float4*>(codebook + (gb + bi) * 8);
        float4* op = reinterpret_cast<float4*>(out + (size_t)grow * (CBN * 8) + cb * 8);
        op[0] = __ldg(cp);
        op[1] = __ldg(cp + 1);
        out[(size_t)B * (CBN * 8) + 1 + (size_t)grow * CBN + cb] = (float)bi;
        sm->bitsv[r] = __ldg(&g_p2[gb + bi]);
    }
    __syncthreads();

    // ---- per-CTA deterministic bits partial ----
    double* bd = sm->dscr;
    bd[tid] = (tid < RPC) ? (double)sm->bitsv[tid] : 0.0;
    __syncthreads();
    #pragma unroll
    for (int off = 128; off > 0; off >>= 1) {
        if (tid < off) bd[tid] += bd[tid + off];
        __syncthreads();
    }
    const int nCTA = gridDim.x * gridDim.y;
    if (tid == 0) {
        g_part[blockIdx.x * gridDim.y + blockIdx.y] = bd[0];
        __threadfence();
        unsigned int old = atomicAdd(&g_ctr, 1u);
        sm->flag = (old == (unsigned)(nCTA - 1)) ? 1 : 0;
    }
    __syncthreads();

    // ---- last CTA: deterministic final bits sum ----
    if (sm->flag) {
        double acc = 0.0;
        for (int i = tid; i < nCTA; i += TPB)
            acc += ((volatile double*)g_part)[i];
        __syncthreads();
        bd[tid] = acc;
        __syncthreads();
        #pragma unroll
        for (int off = 128; off > 0; off >>= 1) {
            if (tid < off) bd[tid] += bd[tid + off];
            __syncthreads();
        }
        if (tid == 0) {
            out[(size_t)B * (CBN * 8)] = (float)bd[0];
            g_ctr = 0;   // reset for next graph replay
        }
    }
}

extern "C" void kernel_launch(void* const* d_in, const int* in_sizes, int n_in,
                              void* d_out, int out_size)
{
    const float* x = nullptr; const float* codebook = nullptr; const float* logits = nullptr;
    int B = 0;
    for (int i = 0; i < n_in; i++) {
        if (in_sizes[i] == CBN * CSZ)          logits   = (const float*)d_in[i];
        else if (in_sizes[i] == CBN * CSZ * 8) codebook = (const float*)d_in[i];
        else { x = (const float*)d_in[i]; B = in_sizes[i] / (CBN * 8); }
    }
    float* out = (float*)d_out;

    size_t smem = sizeof(Smem);
    cudaFuncSetAttribute(ecvq_kernel,
                         cudaFuncAttributeMaxDynamicSharedMemorySize, (int)smem);

    prep_kernel<<<CBN, TPB>>>(codebook, logits);
    dim3 grid(CBN, B / RPC);
    ecvq_kernel<<<grid, TPB, smem>>>(x, codebook, out, B);
}

// round 16
// speedup vs baseline: 1.5593x; 1.5593x over previous
#include <cuda_runtime.h>
#include <cuda_bf16.h>
#include <stdint.h>
#include <math.h>

#define CBN 6
#define CSZ 1024
#define TPB 256
#define RPC 128          // rows per CTA (16 per warp)
#define EPS 0.20f        // rescue window: required ~0.105, 1.9x margin
#define QMAX 320         // per-warp queue entries; flush keeps 256 headroom

// per-lane-region b-frag layout: region (0..31) = g*4+t, stride 130 uint2
// (=1040B, odd 16B multiple -> conflict-free LDS.128), element nt at +nt.
__device__ __align__(16) uint2 g_bfrag[CBN * 32 * 130];
__device__ float  g_c2[CBN * CSZ];
__device__ float  g_L[CBN * CSZ];
__device__ float  g_p2[CBN * CSZ];
__device__ int    g_lc[CBN];
__device__ double g_part[CBN * 256];
__device__ unsigned int g_ctr = 0;

struct __align__(16) Smem {
    uint4  bfrag[32 * 65];            // 33280B
    float4 xfp[2 * RPC];              //  4096B exact fp32 x (rescue)
    unsigned short xaf[RPC * 8];      //  2048B bf16(-2x) a-frags
    float  x2sh[RPC];                 //   512B
    float  bitsv[RPC];                //   512B
    unsigned int qdat[8 * QMAX];      // 10240B per-warp rescue queues
    unsigned long long rbest[RPC];    //  1024B packed (val_bits<<32)|s per row
    double dscr[TPB];                 //  2048B
    int    flag;
};

__device__ __forceinline__ float sqrt_approx(float v) {
    float r; asm("sqrt.approx.f32 %0, %1;" : "=f"(r) : "f"(v)); return r;
}

__device__ __forceinline__ void hmma16816(float& d0, float& d1, float& d2, float& d3,
                                          uint32_t a0, uint32_t a1, uint32_t a2, uint32_t a3,
                                          uint32_t b0, uint32_t b1) {
    asm volatile(
        "mma.sync.aligned.m16n8k16.row.col.f32.bf16.bf16.f32 "
        "{%0,%1,%2,%3}, {%4,%5,%6,%7}, {%8,%9}, {%10,%11,%12,%13};"
        : "=f"(d0), "=f"(d1), "=f"(d2), "=f"(d3)
        : "r"(a0), "r"(a1), "r"(a2), "r"(a3), "r"(b0), "r"(b1),
          "f"(0.0f), "f"(0.0f), "f"(0.0f), "f"(0.0f));
}

// ---------------- prep: per-cb tables (proven numerics chain) ----------------
__global__ void __launch_bounds__(TPB) prep_kernel(
    const float* __restrict__ codebook,
    const float* __restrict__ logits)
{
    __shared__ float scr[TPB];
    const int tid = threadIdx.x;
    const int cb  = blockIdx.x;

    float4 lv = *reinterpret_cast<const float4*>(logits + (size_t)cb * CSZ + tid * 4);
    float lm = fmaxf(fmaxf(lv.x, lv.y), fmaxf(lv.z, lv.w));
    scr[tid] = lm; __syncthreads();
    #pragma unroll
    for (int off = 128; off > 0; off >>= 1) {
        if (tid < off) scr[tid] = fmaxf(scr[tid], scr[tid + off]);
        __syncthreads();
    }
    const float mx = scr[0]; __syncthreads();
    float lmn = fminf(fminf(lv.x, lv.y), fminf(lv.z, lv.w));
    scr[tid] = lmn; __syncthreads();
    #pragma unroll
    for (int off = 128; off > 0; off >>= 1) {
        if (tid < off) scr[tid] = fminf(scr[tid], scr[tid + off]);
        __syncthreads();
    }
    const bool lc = (scr[0] == mx);
    __syncthreads();
    float es = expf(lv.x - mx) + expf(lv.y - mx) + expf(lv.z - mx) + expf(lv.w - mx);
    scr[tid] = es; __syncthreads();
    #pragma unroll
    for (int off = 128; off > 0; off >>= 1) {
        if (tid < off) scr[tid] += scr[tid + off];
        __syncthreads();
    }
    const float lnS = logf(scr[0]);

    const float INV_LOG2 = 1.4426950408889634f;
    #pragma unroll
    for (int j = 0; j < 4; j++) {
        int s = tid * 4 + j;
        const float4* cp = reinterpret_cast<const float4*>(codebook + ((size_t)cb * CSZ + s) * 8);
        float4 c0 = cp[0], c1 = cp[1];
        float q0=c0.x*c0.x,q1=c0.y*c0.y,q2=c0.z*c0.z,q3=c0.w*c0.w;
        float q4=c1.x*c1.x,q5=c1.y*c1.y,q6=c1.z*c1.z,q7=c1.w*c1.w;
        float c2 = ((((((q0+q1)+q2)+q3)+q4)+q5)+q6)+q7;
        float v  = (j==0)?lv.x:(j==1)?lv.y:(j==2)?lv.z:lv.w;
        float p2 = ((v - mx) - lnS) * (-INV_LOG2);
        size_t gi = (size_t)cb * CSZ + s;
        g_c2[gi] = c2;
        g_L[gi]  = p2 / 0.005f;
        g_p2[gi] = p2;
        unsigned short e[8];
        e[0]=__bfloat16_as_ushort(__float2bfloat16_rn(c0.x));
        e[1]=__bfloat16_as_ushort(__float2bfloat16_rn(c0.y));
        e[2]=__bfloat16_as_ushort(__float2bfloat16_rn(c0.z));
        e[3]=__bfloat16_as_ushort(__float2bfloat16_rn(c0.w));
        e[4]=__bfloat16_as_ushort(__float2bfloat16_rn(c1.x));
        e[5]=__bfloat16_as_ushort(__float2bfloat16_rn(c1.y));
        e[6]=__bfloat16_as_ushort(__float2bfloat16_rn(c1.z));
        e[7]=__bfloat16_as_ushort(__float2bfloat16_rn(c1.w));
        unsigned short c2b = __bfloat16_as_ushort(__float2bfloat16_rn(c2));
        int nt = s >> 3, g = s & 7;
        uint2* base = &g_bfrag[(size_t)cb * 4160];
        #pragma unroll
        for (int t = 0; t < 4; t++) {
            uint32_t lo = (uint32_t)e[2*t] | ((uint32_t)e[2*t+1] << 16);
            uint32_t hi = (t == 0) ? (uint32_t)c2b : 0u;   // k8 = c2 (pairs a-frag 1.0)
            base[(g * 4 + t) * 130 + nt] = make_uint2(lo, hi);
        }
    }
    if (tid == 0) g_lc[cb] = lc ? 1 : 0;
}

// ---------------- main ----------------
__global__ void __launch_bounds__(TPB, 4)
ecvq_kernel(const float* __restrict__ x,
            const float* __restrict__ codebook,
            float* __restrict__ out, int B)
{
    extern __shared__ unsigned char smem_raw[];
    Smem* sm = reinterpret_cast<Smem*>(smem_raw);

    const int tid = threadIdx.x;
    const int cb  = blockIdx.x;
    const int rowBase = blockIdx.y * RPC;
    const float FINF = __int_as_float(0x7f800000);
    const size_t gb = (size_t)cb * CSZ;

    // ---- copy b-frag table from gmem (2080 uint4) ----
    {
        const uint4* src = reinterpret_cast<const uint4*>(&g_bfrag[(size_t)cb * 4160]);
        uint4* dst = sm->bfrag;
        #pragma unroll
        for (int i = 0; i < 8; i++) dst[tid + i * TPB] = src[tid + i * TPB];
        if (tid < 2080 - 8 * TPB) dst[tid + 8 * TPB] = src[tid + 8 * TPB];
    }
    const bool lc = (g_lc[cb] != 0);
    const float Lc = __ldg(&g_L[gb]);   // constant L when lc

    // ---- stage x (all 256 threads: half a row each) + init rbest ----
    {
        int r = tid >> 1;               // row 0..127
        int h = tid & 1;                // half
        int grow = rowBase + r;
        const float4* xpp = reinterpret_cast<const float4*>(
            x + (size_t)grow * (CBN * 8) + cb * 8) + h;
        float4 p = *xpp;
        sm->xfp[2 * r + h] = p;
        unsigned short* xa = &sm->xaf[r * 8 + h * 4];
        xa[0] = __bfloat16_as_ushort(__float2bfloat16_rn(-2.0f * p.x));
        xa[1] = __bfloat16_as_ushort(__float2bfloat16_rn(-2.0f * p.y));
        xa[2] = __bfloat16_as_ushort(__float2bfloat16_rn(-2.0f * p.z));
        xa[3] = __bfloat16_as_ushort(__float2bfloat16_rn(-2.0f * p.w));
        if (h == 0) sm->rbest[r] = ((unsigned long long)0x7f800000u << 32) | 0xFFFFFFFFull;
    }
    __syncthreads();
    // exact x2 (one thread per row, same fp32 chain as proven)
    if (tid < RPC) {
        float4 p0 = sm->xfp[2 * tid], p1 = sm->xfp[2 * tid + 1];
        float q0=p0.x*p0.x,q1=p0.y*p0.y,q2=p0.z*p0.z,q3=p0.w*p0.w;
        float q4=p1.x*p1.x,q5=p1.y*p1.y,q6=p1.z*p1.z,q7=p1.w*p1.w;
        sm->x2sh[tid] = ((((((q0+q1)+q2)+q3)+q4)+q5)+q6)+q7;
    }
    __syncthreads();

    // ---- warp tiling: each warp owns 16 rows ----
    const int warp = tid >> 5, lane = tid & 31;
    const int g = lane >> 2, t = lane & 3;
    const int r0 = warp * 16 + g, r1 = r0 + 8;

    const uint32_t a0 = *reinterpret_cast<const uint32_t*>(&sm->xaf[r0 * 8 + t * 2]);
    const uint32_t a1 = *reinterpret_cast<const uint32_t*>(&sm->xaf[r1 * 8 + t * 2]);
    const uint32_t ac = (t == 0) ? 0x00003F80u : 0u;   // bf16(1.0) at k8
    const unsigned lt = (1u << lane) - 1u;

    const char* bp = reinterpret_cast<const char*>(sm->bfrag) + lane * 1040;

    // exact rescore + publish (bit-exact proven chain; batched, warp-cooperative)
    auto flushq = [&](int n) {
        for (int b = 0; b < n; b += 32) {
            int i = b + lane;
            if (i < n) {
                unsigned e = sm->qdat[warp * QMAX + i];
                int s = (int)(e & 1023u), rl = (int)(e >> 10);
                int r = warp * 16 + rl;
                const float4* cp = reinterpret_cast<const float4*>(codebook + (gb + s) * 8);
                float4 ca = __ldg(cp), cv = __ldg(cp + 1);
                float4 pa = sm->xfp[2 * r], pb = sm->xfp[2 * r + 1];
                float xc = pa.x * ca.x;
                xc = fmaf(pa.y, ca.y, xc); xc = fmaf(pa.z, ca.z, xc); xc = fmaf(pa.w, ca.w, xc);
                xc = fmaf(pb.x, cv.x, xc); xc = fmaf(pb.y, cv.y, xc);
                xc = fmaf(pb.z, cv.z, xc); xc = fmaf(pb.w, cv.w, xc);
                float d2 = fmaf(-2.0f, xc, sm->x2sh[r]) + __ldg(&g_c2[gb + s]);
                float L  = lc ? Lc : __ldg(&g_L[gb + s]);
                float val = sqrt_approx(fmaxf(d2, 0.0f)) + L;
                unsigned long long pk =
                    ((unsigned long long)__float_as_uint(val) << 32) | (unsigned long long)(unsigned)s;
                atomicMin(&sm->rbest[r], pk);
            }
        }
    };

    // ============ PASS 1: branchless min of score = c2 - 2xc ============
    float m0 = FINF, m1 = FINF;
    #pragma unroll
    for (int it = 0; it < 64; it++) {
        uint4 q = *reinterpret_cast<const uint4*>(bp + it * 16);
        float d0, d1, d2, d3, e0, e1, e2, e3;
        hmma16816(d0, d1, d2, d3, a0, a1, ac, ac, q.x, q.y);
        hmma16816(e0, e1, e2, e3, a0, a1, ac, ac, q.z, q.w);
        m0 = fminf(m0, fminf(fminf(d0, d1), fminf(e0, e1)));
        m1 = fminf(m1, fminf(fminf(d2, d3), fminf(e2, e3)));
    }
    m0 = fminf(m0, __shfl_xor_sync(0xffffffffu, m0, 1));
    m0 = fminf(m0, __shfl_xor_sync(0xffffffffu, m0, 2));
    m1 = fminf(m1, __shfl_xor_sync(0xffffffffu, m1, 1));
    m1 = fminf(m1, __shfl_xor_sync(0xffffffffu, m1, 2));

    const float thr0 = lc ? m0 + EPS : FINF;
    const float thr1 = lc ? m1 + EPS : FINF;

    // ============ PASS 2: fixed-threshold push to queue ============
    int qn = 0;   // warp-uniform queue count (ballot/popc maintained)

    #define PUSHQ(pred, sval, rlocal) do { \
        unsigned mk = __ballot_sync(0xffffffffu, (pred)); \
        if (pred) sm->qdat[warp * QMAX + qn + __popc(mk & lt)] = \
            (unsigned)((sval) | ((rlocal) << 10)); \
        qn += __popc(mk); \
    } while (0)

    #pragma unroll 8
    for (int it = 0; it < 64; it++) {
        uint4 q = *reinterpret_cast<const uint4*>(bp + it * 16);
        float d0, d1, d2, d3, e0, e1, e2, e3;
        hmma16816(d0, d1, d2, d3, a0, a1, ac, ac, q.x, q.y);
        hmma16816(e0, e1, e2, e3, a0, a1, ac, ac, q.z, q.w);
        bool anyT = (fminf(fminf(d0, d1), fminf(e0, e1)) < thr0)
                  | (fminf(fminf(d2, d3), fminf(e2, e3)) < thr1);
        if (__ballot_sync(0xffffffffu, anyT)) {
            if (qn >= QMAX - 256) { __syncwarp(); flushq(qn); __syncwarp(); qn = 0; }
            int sA = (2 * it) * 8 + 2 * t;
            int sB = sA + 8;
            PUSHQ(d0 < thr0, sA,     g);
            PUSHQ(d1 < thr0, sA + 1, g);
            PUSHQ(d2 < thr1, sA,     g + 8);
            PUSHQ(d3 < thr1, sA + 1, g + 8);
            PUSHQ(e0 < thr0, sB,     g);
            PUSHQ(e1 < thr0, sB + 1, g);
            PUSHQ(e2 < thr1, sB,     g + 8);
            PUSHQ(e3 < thr1, sB + 1, g + 8);
        }
    }
    __syncwarp();
    flushq(qn);
    __syncwarp();

    // ---- epilogue: lanes 0..15 write their row's winner ----
    if (lane < 16) {
        int r = warp * 16 + lane;
        unsigned long long w = sm->rbest[r];
        int bi = (int)(unsigned)(w & 0xFFFFFFFFull);
        int grow = rowBase + r;
        const float4* cp = reinterpret_cast<const float4*>(codebook + (gb + bi) * 8);
        float4* op = reinterpret_cast<float4*>(out + (size_t)grow * (CBN * 8) + cb * 8);
        op[0] = __ldg(cp);
        op[1] = __ldg(cp + 1);
        out[(size_t)B * (CBN * 8) + 1 + (size_t)grow * CBN + cb] = (float)bi;
        sm->bitsv[r] = __ldg(&g_p2[gb + bi]);
    }
    __syncthreads();

    // ---- per-CTA deterministic bits partial ----
    double* bd = sm->dscr;
    bd[tid] = (tid < RPC) ? (double)sm->bitsv[tid] : 0.0;
    __syncthreads();
    #pragma unroll
    for (int off = 128; off > 0; off >>= 1) {
        if (tid < off) bd[tid] += bd[tid + off];
        __syncthreads();
    }
    const int nCTA = gridDim.x * gridDim.y;
    if (tid == 0) {
        g_part[blockIdx.x * gridDim.y + blockIdx.y] = bd[0];
        __threadfence();
        unsigned int old = atomicAdd(&g_ctr, 1u);
        sm->flag = (old == (unsigned)(nCTA - 1)) ? 1 : 0;
    }
    __syncthreads();

    // ---- last CTA: deterministic final bits sum ----
    if (sm->flag) {
        double acc = 0.0;
        for (int i = tid; i < nCTA; i += TPB)
            acc += ((volatile double*)g_part)[i];
        __syncthreads();
        bd[tid] = acc;
        __syncthreads();
        #pragma unroll
        for (int off = 128; off > 0; off >>= 1) {
            if (tid < off) bd[tid] += bd[tid + off];
            __syncthreads();
        }
        if (tid == 0) {
            out[(size_t)B * (CBN * 8)] = (float)bd[0];
            g_ctr = 0;   // reset for next graph replay
        }
    }
}

extern "C" void kernel_launch(void* const* d_in, const int* in_sizes, int n_in,
                              void* d_out, int out_size)
{
    const float* x = nullptr; const float* codebook = nullptr; const float* logits = nullptr;
    int B = 0;
    for (int i = 0; i < n_in; i++) {
        if (in_sizes[i] == CBN * CSZ)          logits   = (const float*)d_in[i];
        else if (in_sizes[i] == CBN * CSZ * 8) codebook = (const float*)d_in[i];
        else { x = (const float*)d_in[i]; B = in_sizes[i] / (CBN * 8); }
    }
    float* out = (float*)d_out;

    size_t smem = sizeof(Smem);
    cudaFuncSetAttribute(ecvq_kernel,
                         cudaFuncAttributeMaxDynamicSharedMemorySize, (int)smem);

    prep_kernel<<<CBN, TPB>>>(codebook, logits);
    dim3 grid(CBN, B / RPC);
    ecvq_kernel<<<grid, TPB, smem>>>(x, codebook, out, B);
}